// round 1
// baseline (speedup 1.0000x reference)
#include <cuda_runtime.h>

// QuantumDotProductCircuit:
//   ov(b) = a(b)^T M b(b),  score = |ov|^2, out = (1+score)/2
// where a,b are real Kronecker product states from RY(tanh(x)*pi) on |0>,
// and M = U_q^dagger U_k is a fixed 16x16 complex matrix built from W_q,W_k.

__device__ ulonglong2 g_M[128];  // 16x16 complex, interleaved (re,im), row-major

__device__ __forceinline__ unsigned long long pk2(float lo, float hi) {
    unsigned long long r;
    asm("mov.b64 %0, {%1, %2};" : "=l"(r) : "f"(lo), "f"(hi));
    return r;
}
__device__ __forceinline__ float2 upk2(unsigned long long v) {
    float2 r;
    asm("mov.b64 {%0, %1}, %2;" : "=f"(r.x), "=f"(r.y) : "l"(v));
    return r;
}
__device__ __forceinline__ unsigned long long fma2(unsigned long long a,
                                                   unsigned long long b,
                                                   unsigned long long c) {
    unsigned long long d;
    asm("fma.rn.f32x2 %0, %1, %2, %3;" : "=l"(d) : "l"(a), "l"(b), "l"(c));
    return d;
}

// ---------------------------------------------------------------------------
// Prep kernel: build U_q, U_k (16x16) by simulating the Rot+CNOT layers on
// each basis state, then M = U_q^dagger U_k. One block, 256 threads.
// Wire w maps to index bit (3-w) (reference reshape puts wire 0 as MSB).
// ---------------------------------------------------------------------------
__global__ void qdp_prep(const float* __restrict__ Wq, const float* __restrict__ Wk) {
    __shared__ float2 U[2][16][16];  // [matrix][row t][column c]
    int tid = threadIdx.x;

    if (tid < 32) {
        int m = tid >> 4;       // 0 = q, 1 = k
        int c = tid & 15;       // column = input basis state
        const float* W = m ? Wk : Wq;

        float vr[16], vi[16];
#pragma unroll
        for (int s = 0; s < 16; s++) { vr[s] = (s == c) ? 1.0f : 0.0f; vi[s] = 0.0f; }

#pragma unroll
        for (int layer = 0; layer < 2; layer++) {
            // Rot(phi, theta, omega) on each wire
#pragma unroll
            for (int w = 0; w < 4; w++) {
                float phi = W[layer * 12 + w * 3 + 0];
                float th  = W[layer * 12 + w * 3 + 1];
                float om  = W[layer * 12 + w * 3 + 2];
                float cth, sth; sincosf(0.5f * th, &sth, &cth);
                float sA, cA, sB, cB;
                sincosf(0.5f * (phi + om), &sA, &cA);   // A
                sincosf(0.5f * (phi - om), &sB, &cB);   // B
                // u00 = e^{-iA} c, u01 = -e^{+iB} s, u10 = e^{-iB} s, u11 = e^{+iA} c
                float u00r =  cA * cth, u00i = -sA * cth;
                float u01r = -cB * sth, u01i = -sB * sth;
                float u10r =  cB * sth, u10i = -sB * sth;
                float u11r =  cA * cth, u11i =  sA * cth;
                const int st = 8 >> w;
#pragma unroll
                for (int s = 0; s < 16; s++) {
                    if (!(s & st)) {
                        const int s1 = s | st;
                        float xr = vr[s], xi = vi[s], yr = vr[s1], yi = vi[s1];
                        vr[s]  = u00r * xr - u00i * xi + u01r * yr - u01i * yi;
                        vi[s]  = u00r * xi + u00i * xr + u01r * yi + u01i * yr;
                        vr[s1] = u10r * xr - u10i * xi + u11r * yr - u11i * yi;
                        vi[s1] = u10r * xi + u10i * xr + u11r * yi + u11i * yr;
                    }
                }
            }
            // CNOT chain: control w, target w+1 -> swap amplitudes where ctrl=1
#pragma unroll
            for (int w = 0; w < 3; w++) {
                const int cm = 8 >> w, tm = 4 >> w;
#pragma unroll
                for (int s = 0; s < 16; s++) {
                    if ((s & cm) && !(s & tm)) {
                        const int s1 = s | tm;
                        float tr = vr[s], ti = vi[s];
                        vr[s] = vr[s1]; vi[s] = vi[s1];
                        vr[s1] = tr;    vi[s1] = ti;
                    }
                }
            }
        }
#pragma unroll
        for (int t = 0; t < 16; t++) U[m][t][c] = make_float2(vr[t], vi[t]);
    }
    __syncthreads();

    // M[i][j] = sum_t conj(Uq[t][i]) * Uk[t][j]
    int i = tid >> 4, j = tid & 15;
    float mr = 0.0f, mi = 0.0f;
#pragma unroll
    for (int t = 0; t < 16; t++) {
        float2 q = U[0][t][i];
        float2 k = U[1][t][j];
        mr += q.x * k.x + q.y * k.y;
        mi += q.x * k.y - q.y * k.x;
    }
    float* gm = (float*)g_M;
    gm[2 * (i * 16 + j) + 0] = mr;
    gm[2 * (i * 16 + j) + 1] = mi;
}

// ---------------------------------------------------------------------------
// Main kernel: one thread per batch element.
// ---------------------------------------------------------------------------
__global__ void qdp_main(const float4* __restrict__ q4, const float4* __restrict__ k4,
                         float* __restrict__ out, int B) {
    __shared__ ulonglong2 Msh[128];
    int tid = threadIdx.x;
    if (tid < 128) Msh[tid] = g_M[tid];
    __syncthreads();

    int idx = blockIdx.x * 256 + tid;
    if (idx >= B) return;

    // rows are 64 floats = 16 float4; we need only the first float4
    float4 qv = q4[(size_t)idx * 16];
    float4 kv = k4[(size_t)idx * 16];

    const float HP = 1.5707963267948966f;  // pi/2 (half-angle scale)
    float cs[4], sn[4];
    {
        float t;
        t = tanhf(qv.x) * HP; __sincosf(t, &sn[0], &cs[0]);
        t = tanhf(qv.y) * HP; __sincosf(t, &sn[1], &cs[1]);
        t = tanhf(qv.z) * HP; __sincosf(t, &sn[2], &cs[2]);
        t = tanhf(qv.w) * HP; __sincosf(t, &sn[3], &cs[3]);
    }
    float a01[4] = {cs[0]*cs[1], cs[0]*sn[1], sn[0]*cs[1], sn[0]*sn[1]};
    float a23[4] = {cs[2]*cs[3], cs[2]*sn[3], sn[2]*cs[3], sn[2]*sn[3]};
    float av[16];
#pragma unroll
    for (int i = 0; i < 16; i++) av[i] = a01[i >> 2] * a23[i & 3];

    {
        float t;
        t = tanhf(kv.x) * HP; __sincosf(t, &sn[0], &cs[0]);
        t = tanhf(kv.y) * HP; __sincosf(t, &sn[1], &cs[1]);
        t = tanhf(kv.z) * HP; __sincosf(t, &sn[2], &cs[2]);
        t = tanhf(kv.w) * HP; __sincosf(t, &sn[3], &cs[3]);
    }
    float b01[4] = {cs[0]*cs[1], cs[0]*sn[1], sn[0]*cs[1], sn[0]*sn[1]};
    float b23[4] = {cs[2]*cs[3], cs[2]*sn[3], sn[2]*cs[3], sn[2]*sn[3]};
    unsigned long long bp[16];
#pragma unroll
    for (int j = 0; j < 16; j++) {
        float v = b01[j >> 2] * b23[j & 3];
        bp[j] = pk2(v, v);
    }

    // ov = sum_i av[i] * (sum_j M[i][j] * b[j]), packed (re,im) lanes
    unsigned long long ov = 0ULL;   // (0.0f, 0.0f)
#pragma unroll
    for (int i = 0; i < 16; i++) {
        unsigned long long t = 0ULL;
#pragma unroll
        for (int jj = 0; jj < 8; jj++) {
            ulonglong2 m = Msh[i * 8 + jj];     // two complex entries
            t = fma2(m.x, bp[2 * jj + 0], t);
            t = fma2(m.y, bp[2 * jj + 1], t);
        }
        ov = fma2(pk2(av[i], av[i]), t, ov);
    }
    float2 o = upk2(ov);
    float score = o.x * o.x + o.y * o.y;
    out[idx] = fmaf(0.5f, score, 0.5f);
}

extern "C" void kernel_launch(void* const* d_in, const int* in_sizes, int n_in,
                              void* d_out, int out_size) {
    const float* q  = (const float*)d_in[0];
    const float* k  = (const float*)d_in[1];
    const float* Wq = (const float*)d_in[2];
    const float* Wk = (const float*)d_in[3];
    int B = in_sizes[0] / 64;

    qdp_prep<<<1, 256>>>(Wq, Wk);
    qdp_main<<<(B + 255) / 256, 256>>>((const float4*)q, (const float4*)k,
                                       (float*)d_out, B);
}

// round 2
// speedup vs baseline: 1.1218x; 1.1218x over previous
#include <cuda_runtime.h>
#include <cuda.h>
#include <cstdint>

// QuantumDotProductCircuit:
//   ov(b) = a(b)^T M b(b),  score = |ov|^2, out = (1+score)/2
// a,b are real Kronecker product states from RY(tanh(x)*pi) on |0>,
// M = U_q^dagger U_k is a fixed 16x16 complex matrix built from W_q,W_k.

__device__ ulonglong2 g_M[128];  // 16x16 complex, interleaved (re,im), row-major

__device__ __forceinline__ unsigned long long pk2(float lo, float hi) {
    unsigned long long r;
    asm("mov.b64 %0, {%1, %2};" : "=l"(r) : "f"(lo), "f"(hi));
    return r;
}
__device__ __forceinline__ float2 upk2(unsigned long long v) {
    float2 r;
    asm("mov.b64 {%0, %1}, %2;" : "=f"(r.x), "=f"(r.y) : "l"(v));
    return r;
}
__device__ __forceinline__ unsigned long long fma2(unsigned long long a,
                                                   unsigned long long b,
                                                   unsigned long long c) {
    unsigned long long d;
    asm("fma.rn.f32x2 %0, %1, %2, %3;" : "=l"(d) : "l"(a), "l"(b), "l"(c));
    return d;
}
__device__ __forceinline__ unsigned long long add2(unsigned long long a,
                                                   unsigned long long b) {
    unsigned long long d;
    asm("add.rn.f32x2 %0, %1, %2;" : "=l"(d) : "l"(a), "l"(b));
    return d;
}
__device__ __forceinline__ uint32_t smem_u32(const void* p) {
    uint32_t a;
    asm("{ .reg .u64 t; cvta.to.shared.u64 t, %1; cvt.u32.u64 %0, t; }" : "=r"(a) : "l"(p));
    return a;
}

// fast tanh: (e^{2x}-1)/(e^{2x}+1), EX2 + RCP.approx. rel err ~1e-6.
__device__ __forceinline__ float fast_tanh(float x) {
    x = fminf(fmaxf(x, -9.0f), 9.0f);
    float e = __expf(2.0f * x);
    return __fdividef(e - 1.0f, e + 1.0f);
}

// ---------------------------------------------------------------------------
// Prep kernel: build U_q, U_k (16x16) by simulating the Rot+CNOT layers on
// each basis state, then M = U_q^dagger U_k. One block, 256 threads.
// Wire w maps to index bit (3-w) (reference reshape puts wire 0 as MSB).
// ---------------------------------------------------------------------------
__global__ void qdp_prep(const float* __restrict__ Wq, const float* __restrict__ Wk) {
    __shared__ float2 U[2][16][16];  // [matrix][row t][column c]
    int tid = threadIdx.x;

    if (tid < 32) {
        int m = tid >> 4;       // 0 = q, 1 = k
        int c = tid & 15;       // column = input basis state
        const float* W = m ? Wk : Wq;

        float vr[16], vi[16];
#pragma unroll
        for (int s = 0; s < 16; s++) { vr[s] = (s == c) ? 1.0f : 0.0f; vi[s] = 0.0f; }

#pragma unroll
        for (int layer = 0; layer < 2; layer++) {
#pragma unroll
            for (int w = 0; w < 4; w++) {
                float phi = W[layer * 12 + w * 3 + 0];
                float th  = W[layer * 12 + w * 3 + 1];
                float om  = W[layer * 12 + w * 3 + 2];
                float cth, sth; __sincosf(0.5f * th, &sth, &cth);
                float sA, cA, sB, cB;
                __sincosf(0.5f * (phi + om), &sA, &cA);
                __sincosf(0.5f * (phi - om), &sB, &cB);
                float u00r =  cA * cth, u00i = -sA * cth;
                float u01r = -cB * sth, u01i = -sB * sth;
                float u10r =  cB * sth, u10i = -sB * sth;
                float u11r =  cA * cth, u11i =  sA * cth;
                const int st = 8 >> w;
#pragma unroll
                for (int s = 0; s < 16; s++) {
                    if (!(s & st)) {
                        const int s1 = s | st;
                        float xr = vr[s], xi = vi[s], yr = vr[s1], yi = vi[s1];
                        vr[s]  = u00r * xr - u00i * xi + u01r * yr - u01i * yi;
                        vi[s]  = u00r * xi + u00i * xr + u01r * yi + u01i * yr;
                        vr[s1] = u10r * xr - u10i * xi + u11r * yr - u11i * yi;
                        vi[s1] = u10r * xi + u10i * xr + u11r * yi + u11i * yr;
                    }
                }
            }
#pragma unroll
            for (int w = 0; w < 3; w++) {
                const int cm = 8 >> w, tm = 4 >> w;
#pragma unroll
                for (int s = 0; s < 16; s++) {
                    if ((s & cm) && !(s & tm)) {
                        const int s1 = s | tm;
                        float tr = vr[s], ti = vi[s];
                        vr[s] = vr[s1]; vi[s] = vi[s1];
                        vr[s1] = tr;    vi[s1] = ti;
                    }
                }
            }
        }
#pragma unroll
        for (int t = 0; t < 16; t++) U[m][t][c] = make_float2(vr[t], vi[t]);
    }
    __syncthreads();

    // M[i][j] = sum_t conj(Uq[t][i]) * Uk[t][j]
    int i = tid >> 4, j = tid & 15;
    float mr = 0.0f, mi = 0.0f;
#pragma unroll
    for (int t = 0; t < 16; t++) {
        float2 q = U[0][t][i];
        float2 k = U[1][t][j];
        mr += q.x * k.x + q.y * k.y;
        mi += q.x * k.y - q.y * k.x;
    }
    float* gm = (float*)g_M;
    gm[2 * (i * 16 + j) + 0] = mr;
    gm[2 * (i * 16 + j) + 1] = mi;
}

// ---------------------------------------------------------------------------
// Shared per-element math: given the first 4 floats of q and k rows,
// compute the output score.
// ---------------------------------------------------------------------------
__device__ __forceinline__ float qdp_element(float4 qv, float4 kv,
                                             const ulonglong2* __restrict__ Msh) {
    const float HP = 1.5707963267948966f;  // pi/2 (half-angle scale)
    float cs[4], sn[4];
    __sincosf(fast_tanh(qv.x) * HP, &sn[0], &cs[0]);
    __sincosf(fast_tanh(qv.y) * HP, &sn[1], &cs[1]);
    __sincosf(fast_tanh(qv.z) * HP, &sn[2], &cs[2]);
    __sincosf(fast_tanh(qv.w) * HP, &sn[3], &cs[3]);
    float a01[4] = {cs[0]*cs[1], cs[0]*sn[1], sn[0]*cs[1], sn[0]*sn[1]};
    float a23[4] = {cs[2]*cs[3], cs[2]*sn[3], sn[2]*cs[3], sn[2]*sn[3]};

    __sincosf(fast_tanh(kv.x) * HP, &sn[0], &cs[0]);
    __sincosf(fast_tanh(kv.y) * HP, &sn[1], &cs[1]);
    __sincosf(fast_tanh(kv.z) * HP, &sn[2], &cs[2]);
    __sincosf(fast_tanh(kv.w) * HP, &sn[3], &cs[3]);
    float b01[4] = {cs[0]*cs[1], cs[0]*sn[1], sn[0]*cs[1], sn[0]*sn[1]};
    float b23[4] = {cs[2]*cs[3], cs[2]*sn[3], sn[2]*cs[3], sn[2]*sn[3]};

    unsigned long long bp[16];
#pragma unroll
    for (int j = 0; j < 16; j++) {
        float v = b01[j >> 2] * b23[j & 3];
        bp[j] = pk2(v, v);
    }

    // ov = sum_i av[i] * (sum_j M[i][j] * b[j]), packed (re,im) lanes.
    // Two inner chains + two outer chains to cover FFMA lat=4 at rt=2.
    unsigned long long ov0 = 0ULL, ov1 = 0ULL;
#pragma unroll
    for (int i = 0; i < 16; i++) {
        unsigned long long t0 = 0ULL, t1 = 0ULL;
#pragma unroll
        for (int jj = 0; jj < 8; jj++) {
            ulonglong2 m = Msh[i * 8 + jj];     // two complex entries
            t0 = fma2(m.x, bp[2 * jj + 0], t0);
            t1 = fma2(m.y, bp[2 * jj + 1], t1);
        }
        float avi = a01[i >> 2] * a23[i & 3];
        unsigned long long avp = pk2(avi, avi);
        unsigned long long s = add2(t0, t1);
        if (i & 1) ov1 = fma2(avp, s, ov1);
        else       ov0 = fma2(avp, s, ov0);
    }
    float2 o = upk2(add2(ov0, ov1));
    float score = o.x * o.x + o.y * o.y;
    return fmaf(0.5f, score, 0.5f);
}

// ---------------------------------------------------------------------------
// Main kernel (TMA path): gather {4 floats x 256 rows} boxes of q and k into
// SMEM via TMA with L2_PROMOTION_NONE (avoid 128B line promotion on the
// strided 16B reads), then one thread per element.
// ---------------------------------------------------------------------------
__global__ void qdp_main_tma(const __grid_constant__ CUtensorMap tq,
                             const __grid_constant__ CUtensorMap tk,
                             float* __restrict__ out, int B) {
    __shared__ __align__(128) float4 sq[256];
    __shared__ __align__(128) float4 sk[256];
    __shared__ ulonglong2 Msh[128];
    __shared__ __align__(8) unsigned long long mbar;

    int tid = threadIdx.x;
    int base = blockIdx.x * 256;
    uint32_t mb = smem_u32(&mbar);

    if (tid == 0) {
        asm volatile("mbarrier.init.shared.b64 [%0], 1;" :: "r"(mb) : "memory");
    }
    __syncthreads();
    if (tid == 0) {
        asm volatile("mbarrier.arrive.expect_tx.shared.b64 _, [%0], %1;"
                     :: "r"(mb), "r"(8192u) : "memory");
        asm volatile("cp.async.bulk.tensor.2d.shared::cta.global.tile.mbarrier::complete_tx::bytes "
                     "[%0], [%1, {%2, %3}], [%4];"
                     :: "r"(smem_u32(sq)), "l"(&tq), "r"(0), "r"(base), "r"(mb) : "memory");
        asm volatile("cp.async.bulk.tensor.2d.shared::cta.global.tile.mbarrier::complete_tx::bytes "
                     "[%0], [%1, {%2, %3}], [%4];"
                     :: "r"(smem_u32(sk)), "l"(&tk), "r"(0), "r"(base), "r"(mb) : "memory");
    }
    // Load M while TMA is in flight
    if (tid < 128) Msh[tid] = g_M[tid];

    // Wait for TMA completion (phase 0)
    {
        uint32_t done;
        asm volatile(
            "{\n\t.reg .pred p;\n\t"
            "mbarrier.try_wait.parity.acquire.cta.shared::cta.b64 p, [%1], %2;\n\t"
            "selp.b32 %0, 1, 0, p;\n\t}"
            : "=r"(done) : "r"(mb), "r"(0u) : "memory");
        if (!done) {
            asm volatile(
                "{\n\t.reg .pred P1;\n\t"
                "W%=:\n\t"
                "mbarrier.try_wait.parity.acquire.cta.shared::cta.b64 P1, [%0], %1, 0x989680;\n\t"
                "@P1 bra.uni D%=;\n\t"
                "bra.uni W%=;\n\t"
                "D%=:\n\t}"
                :: "r"(mb), "r"(0u) : "memory");
        }
    }
    __syncthreads();   // Msh visibility across block

    float4 qv = sq[tid];
    float4 kv = sk[tid];
    float r = qdp_element(qv, kv, Msh);
    int idx = base + tid;
    if (idx < B) out[idx] = r;
}

// ---------------------------------------------------------------------------
// Fallback kernel (LDG path) — identical math, direct strided loads.
// ---------------------------------------------------------------------------
__global__ void qdp_main_ldg(const float4* __restrict__ q4, const float4* __restrict__ k4,
                             float* __restrict__ out, int B) {
    __shared__ ulonglong2 Msh[128];
    int tid = threadIdx.x;
    if (tid < 128) Msh[tid] = g_M[tid];
    __syncthreads();

    int idx = blockIdx.x * 256 + tid;
    if (idx >= B) return;
    float4 qv = q4[(size_t)idx * 16];
    float4 kv = k4[(size_t)idx * 16];
    out[idx] = qdp_element(qv, kv, Msh);
}

// ---------------------------------------------------------------------------
// Host launcher
// ---------------------------------------------------------------------------
typedef CUresult (*PFN_encodeTiled)(
    CUtensorMap*, CUtensorMapDataType, cuuint32_t, void*,
    const cuuint64_t*, const cuuint64_t*, const cuuint32_t*, const cuuint32_t*,
    CUtensorMapInterleave, CUtensorMapSwizzle, CUtensorMapL2promotion,
    CUtensorMapFloatOOBfill);

extern "C" void kernel_launch(void* const* d_in, const int* in_sizes, int n_in,
                              void* d_out, int out_size) {
    const float* q  = (const float*)d_in[0];
    const float* k  = (const float*)d_in[1];
    const float* Wq = (const float*)d_in[2];
    const float* Wk = (const float*)d_in[3];
    int B = in_sizes[0] / 64;
    int nblk = (B + 255) / 256;

    qdp_prep<<<1, 256>>>(Wq, Wk);

    // Resolve cuTensorMapEncodeTiled through cudart (no -lcuda needed)
    PFN_encodeTiled encode = nullptr;
    {
        void* p = nullptr;
        cudaDriverEntryPointQueryResult st = cudaDriverEntryPointSymbolNotFound;
        if (cudaGetDriverEntryPointByVersion("cuTensorMapEncodeTiled", &p, 12050,
                                             cudaEnableDefault, &st) == cudaSuccess &&
            st == cudaDriverEntryPointSuccess && p) {
            encode = (PFN_encodeTiled)p;
        }
    }

    bool tma_ok = false;
    CUtensorMap tq{}, tk{};
    if (encode) {
        cuuint64_t dims[2]    = {64, (cuuint64_t)B};
        cuuint64_t strides[1] = {64 * sizeof(float)};        // 256B row stride
        cuuint32_t box[2]     = {4, 256};                    // 16B x 256 rows
        cuuint32_t estr[2]    = {1, 1};
        CUresult r1 = encode(&tq, CU_TENSOR_MAP_DATA_TYPE_FLOAT32, 2, (void*)q,
                             dims, strides, box, estr,
                             CU_TENSOR_MAP_INTERLEAVE_NONE, CU_TENSOR_MAP_SWIZZLE_NONE,
                             CU_TENSOR_MAP_L2_PROMOTION_NONE,
                             CU_TENSOR_MAP_FLOAT_OOB_FILL_NONE);
        CUresult r2 = encode(&tk, CU_TENSOR_MAP_DATA_TYPE_FLOAT32, 2, (void*)k,
                             dims, strides, box, estr,
                             CU_TENSOR_MAP_INTERLEAVE_NONE, CU_TENSOR_MAP_SWIZZLE_NONE,
                             CU_TENSOR_MAP_L2_PROMOTION_NONE,
                             CU_TENSOR_MAP_FLOAT_OOB_FILL_NONE);
        tma_ok = (r1 == CUDA_SUCCESS && r2 == CUDA_SUCCESS);
    }

    if (tma_ok) {
        qdp_main_tma<<<nblk, 256>>>(tq, tk, (float*)d_out, B);
    } else {
        qdp_main_ldg<<<nblk, 256>>>((const float4*)q, (const float4*)k,
                                    (float*)d_out, B);
    }
}